// round 2
// baseline (speedup 1.0000x reference)
#include <cuda_runtime.h>
#include <cstdint>

#define L_DIM 2048
#define S_DIM 2048
#define D_DIM 128
#define H_DIM 32
#define BM 64
#define BN 64
#define KP 132          // K/V smem pitch in floats (conflict-free QK B loads)
#define MPP 72          // mask/P smem pitch in floats
#define SCALE_F 0.08838834764831845f
#define LOG2E_F 1.4426950408889634f

static __device__ __forceinline__ uint32_t f2tf32(float f) {
    uint32_t u; asm("cvt.rna.tf32.f32 %0, %1;" : "=r"(u) : "f"(f)); return u;
}
static __device__ __forceinline__ float ex2f(float x) {
    float r; asm("ex2.approx.f32 %0, %1;" : "=f"(r) : "f"(x)); return r;
}
static __device__ __forceinline__ void mma8(float* c, const uint32_t* a, uint32_t b0, uint32_t b1) {
    asm volatile("mma.sync.aligned.m16n8k8.row.col.f32.tf32.tf32.f32 "
        "{%0,%1,%2,%3}, {%4,%5,%6,%7}, {%8,%9}, {%0,%1,%2,%3};"
        : "+f"(c[0]), "+f"(c[1]), "+f"(c[2]), "+f"(c[3])
        : "r"(a[0]), "r"(a[1]), "r"(a[2]), "r"(a[3]), "r"(b0), "r"(b1));
}

// Flash attention, TF32 tensor cores, online softmax.
// logits = (Q·K^T + mask) * SCALE ; out = softmax(logits) · V
__global__ void __launch_bounds__(128, 2)
fa_tf32_kernel(const float* __restrict__ q, const float* __restrict__ k,
               const float* __restrict__ v, const float* __restrict__ mask,
               float* __restrict__ out)
{
    extern __shared__ float smem[];
    float* Ks  = smem;               // BN x KP, tf32 bit patterns
    float* Vs  = Ks + BN * KP;       // BN x KP, tf32 bit patterns
    float* MPs = Vs + BN * KP;       // BM x MPP, mask (fp32) then P (tf32 bits)

    const int tid = threadIdx.x;
    const int w  = tid >> 5, ln = tid & 31;
    const int g  = ln >> 2,  c  = ln & 3;       // m16n8k8 fragment coords
    const int h  = blockIdx.y;                  // query head 0..31
    const int kvh = h >> 2;                     // kv head (n_rep = 4)
    const int m0 = blockIdx.x * BM;

    const float* qh = q + (size_t)h   * L_DIM * D_DIM;
    const float* kh = k + (size_t)kvh * S_DIM * D_DIM;
    const float* vh = v + (size_t)kvh * S_DIM * D_DIM;

    const int r0 = m0 + w * 16 + g;             // this thread's first frag row

    // Q fragments, converted to tf32 once, held in registers for all KV tiles.
    uint32_t qa[16][4];
    #pragma unroll
    for (int ks = 0; ks < 16; ks++) {
        qa[ks][0] = f2tf32(qh[(size_t)r0      * D_DIM + ks*8 + c]);
        qa[ks][1] = f2tf32(qh[(size_t)(r0+8)  * D_DIM + ks*8 + c]);
        qa[ks][2] = f2tf32(qh[(size_t)r0      * D_DIM + ks*8 + c + 4]);
        qa[ks][3] = f2tf32(qh[(size_t)(r0+8)  * D_DIM + ks*8 + c + 4]);
    }

    float o[16][4];
    #pragma unroll
    for (int i = 0; i < 16; i++) { o[i][0]=0.f; o[i][1]=0.f; o[i][2]=0.f; o[i][3]=0.f; }
    float m0r = -1e30f, m1r = -1e30f, l0r = 0.f, l1r = 0.f;

    float* MProw0 = &MPs[(w*16 + g)     * MPP];
    float* MProw1 = &MPs[(w*16 + g + 8) * MPP];
    uint32_t* MPu0 = (uint32_t*)MProw0;
    uint32_t* MPu1 = (uint32_t*)MProw1;

    for (int n0 = 0; n0 < S_DIM; n0 += BN) {
        __syncthreads();   // previous iteration fully consumed smem

        // Stage K and V tiles (convert to tf32 once per element).
        #pragma unroll
        for (int it = 0; it < 16; it++) {
            int i = it * 128 + tid;
            int row = i >> 5, c4 = (i & 31) << 2;
            float4 a = *(const float4*)(kh + (size_t)(n0 + row) * D_DIM + c4);
            uint4 b; b.x=f2tf32(a.x); b.y=f2tf32(a.y); b.z=f2tf32(a.z); b.w=f2tf32(a.w);
            *(uint4*)&Ks[row * KP + c4] = b;
            float4 a2 = *(const float4*)(vh + (size_t)(n0 + row) * D_DIM + c4);
            uint4 b2; b2.x=f2tf32(a2.x); b2.y=f2tf32(a2.y); b2.z=f2tf32(a2.z); b2.w=f2tf32(a2.w);
            *(uint4*)&Vs[row * KP + c4] = b2;
        }
        // Stage mask tile (fp32, added before scaling).
        #pragma unroll
        for (int it = 0; it < 8; it++) {
            int i = it * 128 + tid;
            int row = i >> 4, c4 = (i & 15) << 2;
            *(float4*)&MPs[row * MPP + c4] =
                *(const float4*)(mask + (size_t)(m0 + row) * S_DIM + n0 + c4);
        }
        __syncthreads();

        // ---- S = Q · K^T  (per warp: 16 x 64, 8 n-tiles x 16 k-steps) ----
        float sc[8][4];
        #pragma unroll
        for (int j = 0; j < 8; j++) { sc[j][0]=0.f; sc[j][1]=0.f; sc[j][2]=0.f; sc[j][3]=0.f; }
        const uint32_t* Ku = (const uint32_t*)Ks;
        #pragma unroll
        for (int ks = 0; ks < 16; ks++) {
            #pragma unroll
            for (int j = 0; j < 8; j++) {
                uint32_t b0 = Ku[(j*8 + g) * KP + ks*8 + c];
                uint32_t b1 = Ku[(j*8 + g) * KP + ks*8 + c + 4];
                mma8(sc[j], qa[ks], b0, b1);
            }
        }

        // ---- logits = (S + mask) * SCALE ; row max ----
        float rm0 = -1e30f, rm1 = -1e30f;
        #pragma unroll
        for (int j = 0; j < 8; j++) {
            float2 mk0 = *(float2*)&MProw0[j*8 + 2*c];
            float2 mk1 = *(float2*)&MProw1[j*8 + 2*c];
            sc[j][0] = (sc[j][0] + mk0.x) * SCALE_F;
            sc[j][1] = (sc[j][1] + mk0.y) * SCALE_F;
            sc[j][2] = (sc[j][2] + mk1.x) * SCALE_F;
            sc[j][3] = (sc[j][3] + mk1.y) * SCALE_F;
            rm0 = fmaxf(rm0, fmaxf(sc[j][0], sc[j][1]));
            rm1 = fmaxf(rm1, fmaxf(sc[j][2], sc[j][3]));
        }
        rm0 = fmaxf(rm0, __shfl_xor_sync(0xffffffffu, rm0, 1));
        rm0 = fmaxf(rm0, __shfl_xor_sync(0xffffffffu, rm0, 2));
        rm1 = fmaxf(rm1, __shfl_xor_sync(0xffffffffu, rm1, 1));
        rm1 = fmaxf(rm1, __shfl_xor_sync(0xffffffffu, rm1, 2));

        float mn0 = fmaxf(m0r, rm0), mn1 = fmaxf(m1r, rm1);
        float al0 = ex2f((m0r - mn0) * LOG2E_F);
        float al1 = ex2f((m1r - mn1) * LOG2E_F);
        m0r = mn0; m1r = mn1;

        // ---- P = exp(logit - m) ; store tf32 P into warp-private smem rows ----
        float s0 = 0.f, s1 = 0.f;
        #pragma unroll
        for (int j = 0; j < 8; j++) {
            float p00 = ex2f((sc[j][0] - mn0) * LOG2E_F);
            float p01 = ex2f((sc[j][1] - mn0) * LOG2E_F);
            float p10 = ex2f((sc[j][2] - mn1) * LOG2E_F);
            float p11 = ex2f((sc[j][3] - mn1) * LOG2E_F);
            s0 += p00 + p01; s1 += p10 + p11;
            uint2 u0; u0.x = f2tf32(p00); u0.y = f2tf32(p01);
            uint2 u1; u1.x = f2tf32(p10); u1.y = f2tf32(p11);
            *(uint2*)&MPu0[j*8 + 2*c] = u0;
            *(uint2*)&MPu1[j*8 + 2*c] = u1;
        }
        s0 += __shfl_xor_sync(0xffffffffu, s0, 1);
        s0 += __shfl_xor_sync(0xffffffffu, s0, 2);
        s1 += __shfl_xor_sync(0xffffffffu, s1, 1);
        s1 += __shfl_xor_sync(0xffffffffu, s1, 2);
        l0r = l0r * al0 + s0;
        l1r = l1r * al1 + s1;

        #pragma unroll
        for (int dj = 0; dj < 16; dj++) {
            o[dj][0] *= al0; o[dj][1] *= al0;
            o[dj][2] *= al1; o[dj][3] *= al1;
        }
        __syncwarp();   // P visible to all lanes of this warp

        // ---- O += P · V  (8 s-steps x 16 d-tiles) ----
        const uint32_t* Vu = (const uint32_t*)Vs;
        #pragma unroll
        for (int sk = 0; sk < 8; sk++) {
            uint32_t pa[4];
            pa[0] = MPu0[sk*8 + c];
            pa[1] = MPu1[sk*8 + c];
            pa[2] = MPu0[sk*8 + c + 4];
            pa[3] = MPu1[sk*8 + c + 4];
            #pragma unroll
            for (int dj = 0; dj < 16; dj++) {
                uint32_t b0 = Vu[(sk*8 + c)     * KP + dj*8 + g];
                uint32_t b1 = Vu[(sk*8 + c + 4) * KP + dj*8 + g];
                mma8(o[dj], pa, b0, b1);
            }
        }
    }

    // ---- normalize and write out: out[h][l][d], head-major fp32 ----
    float inv0 = 1.f / l0r, inv1 = 1.f / l1r;
    float* oh = out + (size_t)h * L_DIM * D_DIM;
    #pragma unroll
    for (int dj = 0; dj < 16; dj++) {
        float2 t0; t0.x = o[dj][0] * inv0; t0.y = o[dj][1] * inv0;
        float2 t1; t1.x = o[dj][2] * inv1; t1.y = o[dj][3] * inv1;
        *(float2*)&oh[(size_t)r0     * D_DIM + dj*8 + 2*c] = t0;
        *(float2*)&oh[(size_t)(r0+8) * D_DIM + dj*8 + 2*c] = t1;
    }
}

extern "C" void kernel_launch(void* const* d_in, const int* in_sizes, int n_in,
                              void* d_out, int out_size) {
    const float* q    = (const float*)d_in[0];
    const float* k    = (const float*)d_in[1];
    const float* v    = (const float*)d_in[2];
    const float* mask = (const float*)d_in[3];
    float* out = (float*)d_out;

    int smem = (2 * BN * KP + BM * MPP) * (int)sizeof(float);   // 86016 bytes
    cudaFuncSetAttribute(fa_tf32_kernel,
                         cudaFuncAttributeMaxDynamicSharedMemorySize, smem);
    dim3 grid(L_DIM / BM, H_DIM);
    fa_tf32_kernel<<<grid, 128, smem>>>(q, k, v, mask, out);
}

// round 3
// speedup vs baseline: 1.0023x; 1.0023x over previous
#include <cuda_runtime.h>
#include <cstdint>

#define L_DIM 2048
#define S_DIM 2048
#define D_DIM 128
#define H_DIM 32
#define BM 64
#define BN 64
#define KP 132          // K/V smem pitch in floats (conflict-free QK B loads)
#define MPP 72          // mask/P smem pitch in floats
#define SCALE_F 0.08838834764831845f
#define LOG2E_F 1.4426950408889634f

static __device__ __forceinline__ uint32_t f2tf32(float f) {
    uint32_t u; asm("cvt.rna.tf32.f32 %0, %1;" : "=r"(u) : "f"(f)); return u;
}
static __device__ __forceinline__ float ex2f(float x) {
    float r; asm("ex2.approx.f32 %0, %1;" : "=f"(r) : "f"(x)); return r;
}
static __device__ __forceinline__ void mma8(float* c, const uint32_t* a, uint32_t b0, uint32_t b1) {
    asm volatile("mma.sync.aligned.m16n8k8.row.col.f32.tf32.tf32.f32 "
        "{%0,%1,%2,%3}, {%4,%5,%6,%7}, {%8,%9}, {%0,%1,%2,%3};"
        : "+f"(c[0]), "+f"(c[1]), "+f"(c[2]), "+f"(c[3])
        : "r"(a[0]), "r"(a[1]), "r"(a[2]), "r"(a[3]), "r"(b0), "r"(b1));
}

// Flash attention, TF32 tensor cores, online softmax.
// logits = (Q·K^T + mask) * SCALE ; out = softmax(logits) · V
__global__ void __launch_bounds__(128, 2)
fa_tf32_kernel(const float* __restrict__ q, const float* __restrict__ k,
               const float* __restrict__ v, const float* __restrict__ mask,
               float* __restrict__ out)
{
    extern __shared__ float smem[];
    float* Ks  = smem;               // BN x KP, tf32 bit patterns
    float* Vs  = Ks + BN * KP;       // BN x KP, tf32 bit patterns
    float* MPs = Vs + BN * KP;       // BM x MPP, mask (fp32) then P (tf32 bits)

    const int tid = threadIdx.x;
    const int w  = tid >> 5, ln = tid & 31;
    const int g  = ln >> 2,  c  = ln & 3;       // m16n8k8 fragment coords
    const int h  = blockIdx.y;                  // query head 0..31
    const int kvh = h >> 2;                     // kv head (n_rep = 4)
    const int m0 = blockIdx.x * BM;

    const float* qh = q + (size_t)h   * L_DIM * D_DIM;
    const float* kh = k + (size_t)kvh * S_DIM * D_DIM;
    const float* vh = v + (size_t)kvh * S_DIM * D_DIM;

    const int r0 = m0 + w * 16 + g;             // this thread's first frag row

    // Q fragments, converted to tf32 once, held in registers for all KV tiles.
    uint32_t qa[16][4];
    #pragma unroll
    for (int ks = 0; ks < 16; ks++) {
        qa[ks][0] = f2tf32(qh[(size_t)r0      * D_DIM + ks*8 + c]);
        qa[ks][1] = f2tf32(qh[(size_t)(r0+8)  * D_DIM + ks*8 + c]);
        qa[ks][2] = f2tf32(qh[(size_t)r0      * D_DIM + ks*8 + c + 4]);
        qa[ks][3] = f2tf32(qh[(size_t)(r0+8)  * D_DIM + ks*8 + c + 4]);
    }

    float o[16][4];
    #pragma unroll
    for (int i = 0; i < 16; i++) { o[i][0]=0.f; o[i][1]=0.f; o[i][2]=0.f; o[i][3]=0.f; }
    float m0r = -1e30f, m1r = -1e30f, l0r = 0.f, l1r = 0.f;

    float* MProw0 = &MPs[(w*16 + g)     * MPP];
    float* MProw1 = &MPs[(w*16 + g + 8) * MPP];
    uint32_t* MPu0 = (uint32_t*)MProw0;
    uint32_t* MPu1 = (uint32_t*)MProw1;

    for (int n0 = 0; n0 < S_DIM; n0 += BN) {
        __syncthreads();   // previous iteration fully consumed smem

        // Stage K and V tiles (convert to tf32 once per element).
        #pragma unroll
        for (int it = 0; it < 16; it++) {
            int i = it * 128 + tid;
            int row = i >> 5, c4 = (i & 31) << 2;
            float4 a = *(const float4*)(kh + (size_t)(n0 + row) * D_DIM + c4);
            uint4 b; b.x=f2tf32(a.x); b.y=f2tf32(a.y); b.z=f2tf32(a.z); b.w=f2tf32(a.w);
            *(uint4*)&Ks[row * KP + c4] = b;
            float4 a2 = *(const float4*)(vh + (size_t)(n0 + row) * D_DIM + c4);
            uint4 b2; b2.x=f2tf32(a2.x); b2.y=f2tf32(a2.y); b2.z=f2tf32(a2.z); b2.w=f2tf32(a2.w);
            *(uint4*)&Vs[row * KP + c4] = b2;
        }
        // Stage mask tile (fp32, added before scaling).
        #pragma unroll
        for (int it = 0; it < 8; it++) {
            int i = it * 128 + tid;
            int row = i >> 4, c4 = (i & 15) << 2;
            *(float4*)&MPs[row * MPP + c4] =
                *(const float4*)(mask + (size_t)(m0 + row) * S_DIM + n0 + c4);
        }
        __syncthreads();

        // ---- S = Q · K^T  (per warp: 16 x 64, 8 n-tiles x 16 k-steps) ----
        float sc[8][4];
        #pragma unroll
        for (int j = 0; j < 8; j++) { sc[j][0]=0.f; sc[j][1]=0.f; sc[j][2]=0.f; sc[j][3]=0.f; }
        const uint32_t* Ku = (const uint32_t*)Ks;
        #pragma unroll
        for (int ks = 0; ks < 16; ks++) {
            #pragma unroll
            for (int j = 0; j < 8; j++) {
                uint32_t b0 = Ku[(j*8 + g) * KP + ks*8 + c];
                uint32_t b1 = Ku[(j*8 + g) * KP + ks*8 + c + 4];
                mma8(sc[j], qa[ks], b0, b1);
            }
        }

        // ---- logits = (S + mask) * SCALE ; row max ----
        float rm0 = -1e30f, rm1 = -1e30f;
        #pragma unroll
        for (int j = 0; j < 8; j++) {
            float2 mk0 = *(float2*)&MProw0[j*8 + 2*c];
            float2 mk1 = *(float2*)&MProw1[j*8 + 2*c];
            sc[j][0] = (sc[j][0] + mk0.x) * SCALE_F;
            sc[j][1] = (sc[j][1] + mk0.y) * SCALE_F;
            sc[j][2] = (sc[j][2] + mk1.x) * SCALE_F;
            sc[j][3] = (sc[j][3] + mk1.y) * SCALE_F;
            rm0 = fmaxf(rm0, fmaxf(sc[j][0], sc[j][1]));
            rm1 = fmaxf(rm1, fmaxf(sc[j][2], sc[j][3]));
        }
        rm0 = fmaxf(rm0, __shfl_xor_sync(0xffffffffu, rm0, 1));
        rm0 = fmaxf(rm0, __shfl_xor_sync(0xffffffffu, rm0, 2));
        rm1 = fmaxf(rm1, __shfl_xor_sync(0xffffffffu, rm1, 1));
        rm1 = fmaxf(rm1, __shfl_xor_sync(0xffffffffu, rm1, 2));

        float mn0 = fmaxf(m0r, rm0), mn1 = fmaxf(m1r, rm1);
        float al0 = ex2f((m0r - mn0) * LOG2E_F);
        float al1 = ex2f((m1r - mn1) * LOG2E_F);
        m0r = mn0; m1r = mn1;

        // ---- P = exp(logit - m) ; store tf32 P into warp-private smem rows ----
        float s0 = 0.f, s1 = 0.f;
        #pragma unroll
        for (int j = 0; j < 8; j++) {
            float p00 = ex2f((sc[j][0] - mn0) * LOG2E_F);
            float p01 = ex2f((sc[j][1] - mn0) * LOG2E_F);
            float p10 = ex2f((sc[j][2] - mn1) * LOG2E_F);
            float p11 = ex2f((sc[j][3] - mn1) * LOG2E_F);
            s0 += p00 + p01; s1 += p10 + p11;
            uint2 u0; u0.x = f2tf32(p00); u0.y = f2tf32(p01);
            uint2 u1; u1.x = f2tf32(p10); u1.y = f2tf32(p11);
            *(uint2*)&MPu0[j*8 + 2*c] = u0;
            *(uint2*)&MPu1[j*8 + 2*c] = u1;
        }
        s0 += __shfl_xor_sync(0xffffffffu, s0, 1);
        s0 += __shfl_xor_sync(0xffffffffu, s0, 2);
        s1 += __shfl_xor_sync(0xffffffffu, s1, 1);
        s1 += __shfl_xor_sync(0xffffffffu, s1, 2);
        l0r = l0r * al0 + s0;
        l1r = l1r * al1 + s1;

        #pragma unroll
        for (int dj = 0; dj < 16; dj++) {
            o[dj][0] *= al0; o[dj][1] *= al0;
            o[dj][2] *= al1; o[dj][3] *= al1;
        }
        __syncwarp();   // P visible to all lanes of this warp

        // ---- O += P · V  (8 s-steps x 16 d-tiles) ----
        const uint32_t* Vu = (const uint32_t*)Vs;
        #pragma unroll
        for (int sk = 0; sk < 8; sk++) {
            uint32_t pa[4];
            pa[0] = MPu0[sk*8 + c];
            pa[1] = MPu1[sk*8 + c];
            pa[2] = MPu0[sk*8 + c + 4];
            pa[3] = MPu1[sk*8 + c + 4];
            #pragma unroll
            for (int dj = 0; dj < 16; dj++) {
                uint32_t b0 = Vu[(sk*8 + c)     * KP + dj*8 + g];
                uint32_t b1 = Vu[(sk*8 + c + 4) * KP + dj*8 + g];
                mma8(o[dj], pa, b0, b1);
            }
        }
    }

    // ---- normalize and write out: out[h][l][d], head-major fp32 ----
    float inv0 = 1.f / l0r, inv1 = 1.f / l1r;
    float* oh = out + (size_t)h * L_DIM * D_DIM;
    #pragma unroll
    for (int dj = 0; dj < 16; dj++) {
        float2 t0; t0.x = o[dj][0] * inv0; t0.y = o[dj][1] * inv0;
        float2 t1; t1.x = o[dj][2] * inv1; t1.y = o[dj][3] * inv1;
        *(float2*)&oh[(size_t)r0     * D_DIM + dj*8 + 2*c] = t0;
        *(float2*)&oh[(size_t)(r0+8) * D_DIM + dj*8 + 2*c] = t1;
    }
}

extern "C" void kernel_launch(void* const* d_in, const int* in_sizes, int n_in,
                              void* d_out, int out_size) {
    const float* q    = (const float*)d_in[0];
    const float* k    = (const float*)d_in[1];
    const float* v    = (const float*)d_in[2];
    const float* mask = (const float*)d_in[3];
    float* out = (float*)d_out;

    int smem = (2 * BN * KP + BM * MPP) * (int)sizeof(float);   // 86016 bytes
    cudaFuncSetAttribute(fa_tf32_kernel,
                         cudaFuncAttributeMaxDynamicSharedMemorySize, smem);
    dim3 grid(L_DIM / BM, H_DIM);
    fa_tf32_kernel<<<grid, 128, smem>>>(q, k, v, mask, out);
}